// round 5
// baseline (speedup 1.0000x reference)
#include <cuda_runtime.h>
#include <cuda_bf16.h>
#include <cstdint>

// ---------------------------------------------------------------------------
// S4Block on GB300:
//   K0: convert B, C to bf16
//   K1: xB = x @ B^T            (bf16 mma.sync, fp32 accum)
//   K2: s_t = tanh(s_{t-1} A^T + xB_t)  scan; 256 thr/CTA, half-row per thread
//   K3: v = states @ C^T + D*x + x      (residual fused into epilogue)
//   K4: y = LN(v) * gamma + beta        (pure LN pass)
// ---------------------------------------------------------------------------

#define BATCH   16
#define SEQ     2048
#define DM      1024
#define DS      128
#define MTOT    (BATCH * SEQ)          // 32768
#define LN_EPS  1e-5f
#define CH      16                     // xB staging chunk (steps)

// Scratch (device globals; no allocation allowed)
__device__ float          g_xB[MTOT * DS];             // 16 MB
__device__ __nv_bfloat16  g_states[MTOT * DS];         // 8 MB
__device__ __nv_bfloat16  g_Bbf[DS * DM];              // 256 KB
__device__ __nv_bfloat16  g_Cbf[DM * DS];              // 256 KB
__device__ float          g_t[(size_t)MTOT * DM];      // 128 MB

// ---------------------------------------------------------------------------
// helpers
// ---------------------------------------------------------------------------
__device__ __forceinline__ float tanh_fast(float x) {
    float y;
    asm("tanh.approx.f32 %0, %1;" : "=f"(y) : "f"(x));
    return y;
}

typedef unsigned long long u64;
__device__ __forceinline__ u64 pack2(float x, float y) {
    u64 r;
    asm("mov.b64 %0, {%1,%2};" : "=l"(r) : "f"(x), "f"(y));
    return r;
}
__device__ __forceinline__ float2 unpack2(u64 v) {
    float2 f;
    asm("mov.b64 {%0,%1}, %2;" : "=f"(f.x), "=f"(f.y) : "l"(v));
    return f;
}
// packed 2xfp32 FMA (FFMA2): acc = a*b + acc
__device__ __forceinline__ void fma2(u64& acc, u64 a, u64 b) {
    asm("fma.rn.f32x2 %0, %1, %2, %3;" : "=l"(acc) : "l"(a), "l"(b), "l"(acc));
}
// packed 2xfp32 ADD
__device__ __forceinline__ u64 add2(u64 a, u64 b) {
    u64 r;
    asm("add.rn.f32x2 %0, %1, %2;" : "=l"(r) : "l"(a), "l"(b));
    return r;
}

__device__ __forceinline__ void cp16(void* smem, const void* gmem) {
    uint32_t s = (uint32_t)__cvta_generic_to_shared(smem);
    asm volatile("cp.async.cg.shared.global [%0], [%1], 16;" :: "r"(s), "l"(gmem));
}
__device__ __forceinline__ void cp_commit() {
    asm volatile("cp.async.commit_group;");
}
template <int N>
__device__ __forceinline__ void cp_wait() {
    asm volatile("cp.async.wait_group %0;" :: "n"(N));
}

__device__ __forceinline__ void mma_bf16(float* d,
                                         uint32_t a0, uint32_t a1, uint32_t a2, uint32_t a3,
                                         uint32_t b0, uint32_t b1) {
    asm("mma.sync.aligned.m16n8k16.row.col.f32.bf16.bf16.f32 "
        "{%0,%1,%2,%3}, {%4,%5,%6,%7}, {%8,%9}, {%0,%1,%2,%3};"
        : "+f"(d[0]), "+f"(d[1]), "+f"(d[2]), "+f"(d[3])
        : "r"(a0), "r"(a1), "r"(a2), "r"(a3), "r"(b0), "r"(b1));
}

// Shared-tile MMA over one [128m x 32k] x [128n x 32k] chunk.
#define TPAD 40
__device__ __forceinline__ void mma_tile(const __nv_bfloat16* As,
                                         const __nv_bfloat16* Bs,
                                         float acc[2][8][4]) {
    const int lane = threadIdx.x & 31;
    const int warp = threadIdx.x >> 5;
    const int wm = warp >> 1;
    const int wn = warp & 1;
    const int lr = lane >> 2;
    const int lc = (lane & 3) * 2;
#pragma unroll
    for (int kk = 0; kk < 32; kk += 16) {
        uint32_t a[2][4];
#pragma unroll
        for (int mi = 0; mi < 2; mi++) {
            const __nv_bfloat16* p = As + (wm * 32 + mi * 16 + lr) * TPAD + kk + lc;
            a[mi][0] = *(const uint32_t*)p;
            a[mi][1] = *(const uint32_t*)(p + 8 * TPAD);
            a[mi][2] = *(const uint32_t*)(p + 8);
            a[mi][3] = *(const uint32_t*)(p + 8 * TPAD + 8);
        }
        uint32_t b[8][2];
#pragma unroll
        for (int ni = 0; ni < 8; ni++) {
            const __nv_bfloat16* p = Bs + (wn * 64 + ni * 8 + lr) * TPAD + kk + lc;
            b[ni][0] = *(const uint32_t*)p;
            b[ni][1] = *(const uint32_t*)(p + 8);
        }
#pragma unroll
        for (int mi = 0; mi < 2; mi++)
#pragma unroll
            for (int ni = 0; ni < 8; ni++)
                mma_bf16(acc[mi][ni], a[mi][0], a[mi][1], a[mi][2], a[mi][3],
                         b[ni][0], b[ni][1]);
    }
}

// ---------------------------------------------------------------------------
// K0: convert B, C to bf16
// ---------------------------------------------------------------------------
__global__ void k0_convert(const float* __restrict__ B, const float* __restrict__ C) {
    int idx = blockIdx.x * 256 + threadIdx.x;
    if (idx < DS * DM) g_Bbf[idx] = __float2bfloat16(B[idx]);
    if (idx < DM * DS) g_Cbf[idx] = __float2bfloat16(C[idx]);
}

// ---------------------------------------------------------------------------
// K1: xB = x @ B^T.  Grid: 256 CTAs (m-tiles of 128). N = 128 (one tile).
// ---------------------------------------------------------------------------
__global__ void __launch_bounds__(256) k1_xB(const float* __restrict__ x) {
    __shared__ __nv_bfloat16 As[128 * TPAD];
    __shared__ __nv_bfloat16 Bs[128 * TPAD];
    const int t = threadIdx.x;
    const int m0 = blockIdx.x * 128;

    float acc[2][8][4];
#pragma unroll
    for (int i = 0; i < 2; i++)
#pragma unroll
        for (int j = 0; j < 8; j++)
#pragma unroll
            for (int k = 0; k < 4; k++) acc[i][j][k] = 0.f;

    for (int kt = 0; kt < DM; kt += 32) {
#pragma unroll
        for (int pass = 0; pass < 4; pass++) {
            int r = pass * 32 + (t >> 3);
            int c = (t & 7) * 4;
            float4 v = *(const float4*)(x + (size_t)(m0 + r) * DM + kt + c);
            __nv_bfloat162 p0 = __floats2bfloat162_rn(v.x, v.y);
            __nv_bfloat162 p1 = __floats2bfloat162_rn(v.z, v.w);
            *(__nv_bfloat162*)&As[r * TPAD + c]     = p0;
            *(__nv_bfloat162*)&As[r * TPAD + c + 2] = p1;
        }
        {
            int r = t >> 1;
            int half = t & 1;
            const __nv_bfloat16* src = g_Bbf + r * DM + kt + half * 16;
            uint4 v0 = *(const uint4*)(src);
            uint4 v1 = *(const uint4*)(src + 8);
            *(uint4*)&Bs[r * TPAD + half * 16]     = v0;
            *(uint4*)&Bs[r * TPAD + half * 16 + 8] = v1;
        }
        __syncthreads();
        mma_tile(As, Bs, acc);
        __syncthreads();
    }

    const int lane = t & 31, warp = t >> 5;
    const int wm = warp >> 1, wn = warp & 1;
    const int lr = lane >> 2, lc = (lane & 3) * 2;
#pragma unroll
    for (int mi = 0; mi < 2; mi++)
#pragma unroll
        for (int ni = 0; ni < 8; ni++) {
            int row = m0 + wm * 32 + mi * 16 + lr;
            int col = wn * 64 + ni * 8 + lc;
            float* o0 = g_xB + (size_t)row * DS + col;
            float* o1 = g_xB + (size_t)(row + 8) * DS + col;
            *(float2*)o0 = make_float2(acc[mi][ni][0], acc[mi][ni][1]);
            *(float2*)o1 = make_float2(acc[mi][ni][2], acc[mi][ni][3]);
        }
}

// ---------------------------------------------------------------------------
// K2: recurrence. 16 CTAs (one per batch) x 256 threads.
// Thread (i = t>>1, h = t&1) owns half-row h of A row i: 32 f32x2 in regs.
// State broadcast via LDS.128 (2 bcast addrs/warp), pair-reduce via shfl.
// h==0 lane: STS next state; h==1 lane: STG to g_states (parallel stores).
// ---------------------------------------------------------------------------
__global__ void __launch_bounds__(256, 1) k2_scan(const float* __restrict__ A) {
    const int b = blockIdx.x;
    const int t = threadIdx.x;
    const int i = t >> 1;
    const int h = t & 1;

    __shared__ float s_sh[2][DS];
    __shared__ float xb_sh[2][CH * DS];    // 2 x 8KB

    // A[i][h*64 .. h*64+63] as 32 packed f32x2
    u64 a[32];
#pragma unroll
    for (int u = 0; u < 32; u++) {
        float2 v = *(const float2*)(A + i * DS + h * 64 + 2 * u);
        a[u] = pack2(v.x, v.y);
    }

    const float* xb = g_xB + (size_t)b * SEQ * DS;
    __nv_bfloat16* so = g_states + (size_t)b * SEQ * DS;

    // preload chunks 0 and 1 (each 8KB: 256 threads x 2 x 16B)
#pragma unroll
    for (int q = 0; q < 2; q++)
        cp16(&xb_sh[0][(q * 256 + t) * 4], xb + (q * 256 + t) * 4);
    cp_commit();
#pragma unroll
    for (int q = 0; q < 2; q++)
        cp16(&xb_sh[1][(q * 256 + t) * 4], xb + CH * DS + (q * 256 + t) * 4);
    cp_commit();

    if (t < DS) { s_sh[0][t] = 0.f; s_sh[1][t] = 0.f; }
    __syncthreads();

    for (int c = 0; c < SEQ / CH; c++) {
        cp_wait<1>();          // chunk c resident
        __syncthreads();

        const float* xbc = xb_sh[c & 1];
#pragma unroll 1
        for (int k = 0; k < CH; k++) {
            const int tt = c * CH + k;
            const ulonglong2* sv = (const ulonglong2*)(s_sh[tt & 1] + h * 64);
            u64 ac0 = 0ull, ac1 = 0ull, ac2 = 0ull, ac3 = 0ull;
            u64 ac4 = 0ull, ac5 = 0ull, ac6 = 0ull, ac7 = 0ull;
#pragma unroll
            for (int u = 0; u < 16; u += 4) {
                ulonglong2 w0 = sv[u + 0];
                ulonglong2 w1 = sv[u + 1];
                ulonglong2 w2 = sv[u + 2];
                ulonglong2 w3 = sv[u + 3];
                fma2(ac0, a[2 * u + 0], w0.x);
                fma2(ac1, a[2 * u + 1], w0.y);
                fma2(ac2, a[2 * u + 2], w1.x);
                fma2(ac3, a[2 * u + 3], w1.y);
                fma2(ac4, a[2 * u + 4], w2.x);
                fma2(ac5, a[2 * u + 5], w2.y);
                fma2(ac6, a[2 * u + 6], w3.x);
                fma2(ac7, a[2 * u + 7], w3.y);
            }
            u64 s0 = add2(add2(ac0, ac1), add2(ac2, ac3));
            u64 s1 = add2(add2(ac4, ac5), add2(ac6, ac7));
            float2 f = unpack2(add2(s0, s1));
            float vh = f.x + f.y;
            float v = vh + __shfl_xor_sync(0xffffffffu, vh, 1);
            float s = tanh_fast(v + xbc[k * DS + i]);
            if (h == 0) s_sh[(tt + 1) & 1][i] = s;
            if (h == 1) so[tt * DS + i] = __float2bfloat16(s);
            __syncthreads();
        }

        // prefetch chunk c+2 into the buffer just consumed
        if (c + 2 < SEQ / CH) {
            const float* src = xb + (size_t)(c + 2) * CH * DS;
#pragma unroll
            for (int q = 0; q < 2; q++)
                cp16(&xb_sh[c & 1][(q * 256 + t) * 4], src + (q * 256 + t) * 4);
        }
        cp_commit();
    }
}

// ---------------------------------------------------------------------------
// K3: v = states @ C^T + D*x + x  -> g_t.  Grid: (256 m-tiles, 8 n-tiles).
// ---------------------------------------------------------------------------
__global__ void __launch_bounds__(256) k3_out(const float* __restrict__ x,
                                              const float* __restrict__ D) {
    __shared__ __nv_bfloat16 As[128 * TPAD];
    __shared__ __nv_bfloat16 Bs[128 * TPAD];
    const int t = threadIdx.x;
    const int m0 = blockIdx.x * 128;
    const int n0 = blockIdx.y * 128;

    float acc[2][8][4];
#pragma unroll
    for (int i = 0; i < 2; i++)
#pragma unroll
        for (int j = 0; j < 8; j++)
#pragma unroll
            for (int k = 0; k < 4; k++) acc[i][j][k] = 0.f;

    for (int kt = 0; kt < DS; kt += 32) {
        {
            int r = t >> 1;
            int half = t & 1;
            const __nv_bfloat16* src = g_states + (size_t)(m0 + r) * DS + kt + half * 16;
            uint4 v0 = *(const uint4*)(src);
            uint4 v1 = *(const uint4*)(src + 8);
            *(uint4*)&As[r * TPAD + half * 16]     = v0;
            *(uint4*)&As[r * TPAD + half * 16 + 8] = v1;
        }
        {
            int r = t >> 1;
            int half = t & 1;
            const __nv_bfloat16* src = g_Cbf + (n0 + r) * DS + kt + half * 16;
            uint4 v0 = *(const uint4*)(src);
            uint4 v1 = *(const uint4*)(src + 8);
            *(uint4*)&Bs[r * TPAD + half * 16]     = v0;
            *(uint4*)&Bs[r * TPAD + half * 16 + 8] = v1;
        }
        __syncthreads();
        mma_tile(As, Bs, acc);
        __syncthreads();
    }

    const int lane = t & 31, warp = t >> 5;
    const int wm = warp >> 1, wn = warp & 1;
    const int lr = lane >> 2, lc = (lane & 3) * 2;
#pragma unroll
    for (int mi = 0; mi < 2; mi++)
#pragma unroll
        for (int ni = 0; ni < 8; ni++) {
            int row = m0 + wm * 32 + mi * 16 + lr;
            int col = n0 + wn * 64 + ni * 8 + lc;
            float2 d2 = *(const float2*)(D + col);
            float2 x0 = *(const float2*)(x + (size_t)row * DM + col);
            float2 x1 = *(const float2*)(x + (size_t)(row + 8) * DM + col);
            float* o0 = g_t + (size_t)row * DM + col;
            float* o1 = g_t + (size_t)(row + 8) * DM + col;
            *(float2*)o0 = make_float2(acc[mi][ni][0] + (d2.x + 1.f) * x0.x,
                                       acc[mi][ni][1] + (d2.y + 1.f) * x0.y);
            *(float2*)o1 = make_float2(acc[mi][ni][2] + (d2.x + 1.f) * x1.x,
                                       acc[mi][ni][3] + (d2.y + 1.f) * x1.y);
        }
}

// ---------------------------------------------------------------------------
// K4: y = LN(v) * gamma + beta.  One CTA (256 thr) per row; v = g_t row.
// ---------------------------------------------------------------------------
__global__ void __launch_bounds__(256) k4_ln(const float* __restrict__ gamma,
                                             const float* __restrict__ beta,
                                             float* __restrict__ y) {
    const int m = blockIdx.x;
    const int t = threadIdx.x;
    const int c = t * 4;

    float4 v = *(const float4*)(g_t + (size_t)m * DM + c);

    float s = v.x + v.y + v.z + v.w;
    float q = v.x * v.x + v.y * v.y + v.z * v.z + v.w * v.w;
#pragma unroll
    for (int o = 16; o > 0; o >>= 1) {
        s += __shfl_xor_sync(0xffffffffu, s, o);
        q += __shfl_xor_sync(0xffffffffu, q, o);
    }
    __shared__ float ss[8], qq[8];
    __shared__ float mu_s, rs_s;
    if ((t & 31) == 0) { ss[t >> 5] = s; qq[t >> 5] = q; }
    __syncthreads();
    if (t == 0) {
        float S = 0.f, Q = 0.f;
#pragma unroll
        for (int w = 0; w < 8; w++) { S += ss[w]; Q += qq[w]; }
        float mu = S * (1.f / DM);
        float var = Q * (1.f / DM) - mu * mu;
        mu_s = mu;
        rs_s = rsqrtf(var + LN_EPS);
    }
    __syncthreads();
    float mu = mu_s, rs = rs_s;

    float4 g4 = *(const float4*)(gamma + c);
    float4 b4 = *(const float4*)(beta + c);
    float4 out;
    out.x = (v.x - mu) * rs * g4.x + b4.x;
    out.y = (v.y - mu) * rs * g4.y + b4.y;
    out.z = (v.z - mu) * rs * g4.z + b4.z;
    out.w = (v.w - mu) * rs * g4.w + b4.w;
    *(float4*)(y + (size_t)m * DM + c) = out;
}

// ---------------------------------------------------------------------------
extern "C" void kernel_launch(void* const* d_in, const int* in_sizes, int n_in,
                              void* d_out, int out_size) {
    const float* x     = (const float*)d_in[0];
    const float* A     = (const float*)d_in[1];
    const float* B     = (const float*)d_in[2];
    const float* C     = (const float*)d_in[3];
    const float* D     = (const float*)d_in[4];
    const float* gamma = (const float*)d_in[5];
    const float* beta  = (const float*)d_in[6];
    float* y = (float*)d_out;

    k0_convert<<<512, 256>>>(B, C);
    k1_xB<<<MTOT / 128, 256>>>(x);
    k2_scan<<<BATCH, 256>>>(A);
    k3_out<<<dim3(MTOT / 128, DM / 128), 256>>>(x, D);
    k4_ln<<<MTOT, 256>>>(gamma, beta, y);
}